// round 3
// baseline (speedup 1.0000x reference)
#include <cuda_runtime.h>
#include <math.h>

#define BB 32
#define LL 196
#define DD 512
#define HH 8
#define DHH 64
#define MM (BB*LL)              // 6272

// ---------------- scratch (static device allocations; no malloc) -------------
__device__ float g_Q[MM*DD];
__device__ float g_K[MM*DD];
__device__ float g_V[MM*DD];
__device__ float g_ctx[MM*DD];
__device__ float g_rowmax[BB*BB*LL];
__device__ float g_colmax[BB*BB*LL];

static const size_t OUT_CTX    = 0;
static const size_t OUT_LOGITS = (size_t)MM*DD;              // 3,211,264
static const size_t OUT_PROBS  = (size_t)MM*DD + BB*BB;      // 3,212,288

// float atomic max via signed/unsigned monotonicity trick (init = -inf)
__device__ __forceinline__ void atomicMaxF(float* addr, float v){
    if (v >= 0.0f) atomicMax((int*)addr, __float_as_int(v));
    else           atomicMin((unsigned int*)addr, __float_as_uint(v));
}

// ---------------- K0: init row/col max scratch -------------------------------
__global__ void init_kernel(){
    int i = blockIdx.x*blockDim.x + threadIdx.x;
    if (i < BB*BB*LL){ g_rowmax[i] = -INFINITY; g_colmax[i] = -INFINITY; }
}

// ---------------- K1: QKV projection C = X @ W^T + b -------------------------
// 64x64 tile, BK=16, 256 threads, 4x4 micro-tile, float4 smem paths.
__global__ __launch_bounds__(256) void proj_kernel(
    const float* __restrict__ Xq, const float* __restrict__ Xk, const float* __restrict__ Xv,
    const float* __restrict__ Wq, const float* __restrict__ bq,
    const float* __restrict__ Wk, const float* __restrict__ bk,
    const float* __restrict__ Wv, const float* __restrict__ bv)
{
    int z = blockIdx.z;
    const float* X = (z==0)? Xq : (z==1)? Xk : Xv;
    const float* W = (z==0)? Wq : (z==1)? Wk : Wv;
    const float* bias = (z==0)? bq : (z==1)? bk : bv;
    float* dst = (z==0)? g_Q : (z==1)? g_K : g_V;

    __shared__ float As[16][68];   // 68 floats = 272B, 16B-divisible -> float4 ok
    __shared__ float Bs[16][68];

    int tid = threadIdx.x;
    int tx = tid & 15, ty = tid >> 4;
    int row0 = blockIdx.y * 64;
    int col0 = blockIdx.x * 64;

    float acc[4][4] = {};

    for (int k0 = 0; k0 < DD; k0 += 16){
        // load 64x16 A and B tiles, 4 floats/thread via float4
        int m   = tid >> 2;
        int kk0 = (tid & 3) * 4;
        float4 va = *(const float4*)(X + (size_t)(row0 + m)*DD + k0 + kk0);
        As[kk0+0][m]=va.x; As[kk0+1][m]=va.y; As[kk0+2][m]=va.z; As[kk0+3][m]=va.w;
        float4 vb = *(const float4*)(W + (size_t)(col0 + m)*DD + k0 + kk0);
        Bs[kk0+0][m]=vb.x; Bs[kk0+1][m]=vb.y; Bs[kk0+2][m]=vb.z; Bs[kk0+3][m]=vb.w;
        __syncthreads();

        #pragma unroll
        for (int kk = 0; kk < 16; kk++){
            float4 a4 = *(const float4*)&As[kk][ty*4];
            float4 b4 = *(const float4*)&Bs[kk][tx*4];
            float a[4] = {a4.x,a4.y,a4.z,a4.w};
            float b[4] = {b4.x,b4.y,b4.z,b4.w};
            #pragma unroll
            for (int i=0;i<4;i++)
                #pragma unroll
                for (int j=0;j<4;j++)
                    acc[i][j] += a[i]*b[j];
        }
        __syncthreads();
    }

    #pragma unroll
    for (int i=0;i<4;i++){
        int r = row0 + ty*4 + i;
        #pragma unroll
        for (int j=0;j<4;j++){
            int c = col0 + tx*4 + j;
            dst[(size_t)r*DD + c] = acc[i][j] + bias[c];
        }
    }
}

// ---------------- K2: retrieval GEMM + row/col max ---------------------------
// C = Q[a] (196x512) @ K[b]^T (196x512)^T, one CTA per (a,b, 98x98 quadrant).
// 196 threads = 14x14, each a 7x7 micro-tile. BK=8.
__global__ __launch_bounds__(224) void retrieve_kernel(){
    int p = blockIdx.z;                  // pair id
    int a = p >> 5, b = p & 31;
    int rowBlk = blockIdx.y;             // 0..1
    int colBlk = blockIdx.x;             // 0..1

    __shared__ float As[8][100];
    __shared__ float Bs[8][100];

    int tid = threadIdx.x;               // 0..195
    int tx = tid % 14, ty = tid / 14;

    const float* Qbase = g_Q + (size_t)(a*LL + rowBlk*98)*DD;
    const float* Kbase = g_K + (size_t)(b*LL + colBlk*98)*DD;

    float acc[7][7] = {};

    int e   = tid * 4;                   // 0..783
    int lr  = e >> 3;                    // row 0..97
    int lk0 = e & 7;                     // 0 or 4

    for (int k0 = 0; k0 < DD; k0 += 8){
        float4 va = *(const float4*)(Qbase + (size_t)lr*DD + k0 + lk0);
        As[lk0+0][lr]=va.x; As[lk0+1][lr]=va.y; As[lk0+2][lr]=va.z; As[lk0+3][lr]=va.w;
        float4 vb = *(const float4*)(Kbase + (size_t)lr*DD + k0 + lk0);
        Bs[lk0+0][lr]=vb.x; Bs[lk0+1][lr]=vb.y; Bs[lk0+2][lr]=vb.z; Bs[lk0+3][lr]=vb.w;
        __syncthreads();

        #pragma unroll
        for (int kk = 0; kk < 8; kk++){
            float ar[7], br[7];
            #pragma unroll
            for (int i=0;i<7;i++) ar[i] = As[kk][ty*7+i];
            #pragma unroll
            for (int j=0;j<7;j++) br[j] = Bs[kk][tx*7+j];
            #pragma unroll
            for (int i=0;i<7;i++)
                #pragma unroll
                for (int j=0;j<7;j++)
                    acc[i][j] += ar[i]*br[j];
        }
        __syncthreads();
    }

    float* rmax = g_rowmax + (size_t)p*LL + rowBlk*98;
    float* cmax = g_colmax + (size_t)p*LL + colBlk*98;
    #pragma unroll
    for (int i=0;i<7;i++){
        float m = acc[i][0];
        #pragma unroll
        for (int j=1;j<7;j++) m = fmaxf(m, acc[i][j]);
        atomicMaxF(&rmax[ty*7+i], m);
    }
    #pragma unroll
    for (int j=0;j<7;j++){
        float m = acc[0][j];
        #pragma unroll
        for (int i=1;i<7;i++) m = fmaxf(m, acc[i][j]);
        atomicMaxF(&cmax[tx*7+j], m);
    }
}

// ---------------- K3: logits reduce ------------------------------------------
__global__ __launch_bounds__(256) void logits_kernel(const float* __restrict__ ls,
                                                     float* __restrict__ out){
    int p = blockIdx.x;                  // 0..1023
    int t = threadIdx.x;
    float v = 0.0f;
    if (t < LL) v = g_rowmax[(size_t)p*LL + t] + g_colmax[(size_t)p*LL + t];
    // block sum
    #pragma unroll
    for (int o=16;o;o>>=1) v += __shfl_xor_sync(0xffffffffu, v, o);
    __shared__ float red[8];
    if ((t & 31) == 0) red[t >> 5] = v;
    __syncthreads();
    if (t == 0){
        float s = 0.0f;
        #pragma unroll
        for (int w=0; w<8; w++) s += red[w];
        out[p] = expf(ls[0]) * s / (2.0f * (float)LL);
    }
}

// ---------------- K4: self-attention per (b,h) -------------------------------
// smem: Ks[196*65] Vs[196*65] qsh[8*64] psh[8*200]  = 110,368 B
#define ATTN_SMEM ((196*65*2 + 8*64 + 8*200) * (int)sizeof(float))

__global__ __launch_bounds__(256) void attn_kernel(float* __restrict__ out_probs){
    int h = blockIdx.x, b = blockIdx.y;
    extern __shared__ float sm[];
    float* Ks  = sm;                       // [m*65 + d]
    float* Vs  = sm + 196*65;
    float* qsh = sm + 196*65*2;            // per-warp 64
    float* psh = qsh + 8*64;               // per-warp 200

    int tid = threadIdx.x;
    int w = tid >> 5, lane = tid & 31;

    const float* Kg = g_K + (size_t)(b*LL)*DD + h*DHH;
    const float* Vg = g_V + (size_t)(b*LL)*DD + h*DHH;

    for (int i = tid; i < LL*16; i += 256){
        int m = i >> 4, d4 = (i & 15) * 4;
        float4 kv = *(const float4*)(Kg + (size_t)m*DD + d4);
        Ks[m*65+d4]=kv.x; Ks[m*65+d4+1]=kv.y; Ks[m*65+d4+2]=kv.z; Ks[m*65+d4+3]=kv.w;
        float4 vv = *(const float4*)(Vg + (size_t)m*DD + d4);
        Vs[m*65+d4]=vv.x; Vs[m*65+d4+1]=vv.y; Vs[m*65+d4+2]=vv.z; Vs[m*65+d4+3]=vv.w;
    }
    __syncthreads();

    float* qw = qsh + w*64;
    float* pw = psh + w*200;

    for (int l = w; l < LL; l += 8){
        const float* qrow = g_Q + (size_t)(b*LL + l)*DD + h*DHH;
        qw[lane]      = qrow[lane];
        qw[lane + 32] = qrow[lane + 32];
        __syncwarp();

        // scores: lane handles m = lane + 32*mi (clamped loads, masked later)
        int mm[7]; bool valid[7];
        #pragma unroll
        for (int mi=0;mi<7;mi++){
            int m = lane + mi*32;
            valid[mi] = (m < LL);
            mm[mi] = valid[mi] ? m : (LL-1);
        }
        float s[7] = {};
        for (int d = 0; d < DHH; d++){
            float qd = qw[d];
            #pragma unroll
            for (int mi=0;mi<7;mi++)
                s[mi] += qd * Ks[mm[mi]*65 + d];
        }
        float mx = -INFINITY;
        #pragma unroll
        for (int mi=0;mi<7;mi++){
            s[mi] = valid[mi] ? s[mi]*0.125f : -INFINITY;
            mx = fmaxf(mx, s[mi]);
        }
        #pragma unroll
        for (int o=16;o;o>>=1) mx = fmaxf(mx, __shfl_xor_sync(0xffffffffu, mx, o));
        float sum = 0.0f;
        #pragma unroll
        for (int mi=0;mi<7;mi++){ float e = expf(s[mi]-mx); s[mi]=e; sum+=e; }
        #pragma unroll
        for (int o=16;o;o>>=1) sum += __shfl_xor_sync(0xffffffffu, sum, o);
        float inv = 1.0f / sum;

        float* pmrow = out_probs + (size_t)(b*LL + l)*LL;
        #pragma unroll
        for (int mi=0;mi<7;mi++){
            if (valid[mi]){
                float pv = s[mi]*inv;
                pw[mm[mi]] = pv;
                atomicAdd(&pmrow[mm[mi]], pv * 0.125f);   // mean over 8 heads
            }
        }
        __syncwarp();

        // ctx row: lane owns dims lane and lane+32
        float c0 = 0.0f, c1 = 0.0f;
        for (int m = 0; m < LL; m++){
            float pm = pw[m];
            c0 += pm * Vs[m*65 + lane];
            c1 += pm * Vs[m*65 + 32 + lane];
        }
        float* crow = g_ctx + (size_t)(b*LL + l)*DD + h*DHH;
        crow[lane]      = c0;
        crow[lane + 32] = c1;
        __syncwarp();
    }
}

// ---------------- K5: residual + LayerNorm -----------------------------------
__global__ __launch_bounds__(128) void ln_kernel(const float* __restrict__ qin,
                                                 const float* __restrict__ gamma,
                                                 const float* __restrict__ beta,
                                                 float* __restrict__ out){
    int row = blockIdx.x;
    int t = threadIdx.x;
    const float* c = g_ctx + (size_t)row*DD;
    const float* q = qin   + (size_t)row*DD;
    __shared__ float red[4];

    float v[4]; float s = 0.0f;
    #pragma unroll
    for (int i=0;i<4;i++){ v[i] = c[t + i*128] + q[t + i*128]; s += v[i]; }
    #pragma unroll
    for (int o=16;o;o>>=1) s += __shfl_xor_sync(0xffffffffu, s, o);
    if ((t & 31) == 0) red[t>>5] = s;
    __syncthreads();
    float mu = (red[0]+red[1]+red[2]+red[3]) * (1.0f/DD);
    __syncthreads();

    float s2 = 0.0f;
    #pragma unroll
    for (int i=0;i<4;i++){ float d = v[i]-mu; s2 += d*d; }
    #pragma unroll
    for (int o=16;o;o>>=1) s2 += __shfl_xor_sync(0xffffffffu, s2, o);
    if ((t & 31) == 0) red[t>>5] = s2;
    __syncthreads();
    float var = (red[0]+red[1]+red[2]+red[3]) * (1.0f/DD);
    float invs = rsqrtf(var + 1e-6f);

    #pragma unroll
    for (int i=0;i<4;i++){
        int col = t + i*128;
        out[(size_t)row*DD + col] = (v[i]-mu)*invs*gamma[col] + beta[col];
    }
}

// ---------------- launch ------------------------------------------------------
extern "C" void kernel_launch(void* const* d_in, const int* in_sizes, int n_in,
                              void* d_out, int out_size)
{
    const float* q  = (const float*)d_in[0];
    const float* k  = (const float*)d_in[1];
    const float* v  = (const float*)d_in[2];
    const float* Wq = (const float*)d_in[3];
    const float* bq = (const float*)d_in[4];
    const float* Wk = (const float*)d_in[5];
    const float* bk = (const float*)d_in[6];
    const float* Wv = (const float*)d_in[7];
    const float* bv = (const float*)d_in[8];
    const float* gamma = (const float*)d_in[9];
    const float* beta  = (const float*)d_in[10];
    const float* ls    = (const float*)d_in[11];
    float* out = (float*)d_out;

    cudaFuncSetAttribute(attn_kernel, cudaFuncAttributeMaxDynamicSharedMemorySize, ATTN_SMEM);

    init_kernel<<<(BB*BB*LL + 255)/256, 256>>>();
    cudaMemsetAsync(out + OUT_PROBS, 0, (size_t)BB*LL*LL*sizeof(float));

    proj_kernel<<<dim3(DD/64, MM/64, 3), 256>>>(q, k, v, Wq, bq, Wk, bk, Wv, bv);

    retrieve_kernel<<<dim3(2, 2, BB*BB), 196>>>();

    attn_kernel<<<dim3(HH, BB), 256, ATTN_SMEM>>>(out + OUT_PROBS);

    logits_kernel<<<BB*BB, 256>>>(ls, out + OUT_LOGITS);

    ln_kernel<<<MM, 128>>>(q, gamma, beta, out + OUT_CTX);
}

// round 7
// speedup vs baseline: 2.3416x; 2.3416x over previous
#include <cuda_runtime.h>
#include <cuda_bf16.h>
#include <math.h>
#include <stdint.h>

#define BB 32
#define LL 196
#define DD 512
#define HH 8
#define DHH 64
#define MM (BB*LL)              // 6272

// ---------------- scratch (static device allocations; no malloc) -------------
__device__ float g_Q[MM*DD];
__device__ float g_K[MM*DD];
__device__ float g_V[MM*DD];
__device__ float g_ctx[MM*DD];
__device__ __nv_bfloat16 g_Qbf[MM*DD];
__device__ __nv_bfloat16 g_Kbf[MM*DD];
__device__ float g_rowmax[BB*BB*LL];
__device__ float g_colmax[BB*BB*LL];

static const size_t OUT_CTX    = 0;
static const size_t OUT_LOGITS = (size_t)MM*DD;              // 3,211,264
static const size_t OUT_PROBS  = (size_t)MM*DD + BB*BB;      // 3,212,288

// float atomic max via signed/unsigned monotonicity trick (init = -inf)
__device__ __forceinline__ void atomicMaxF(float* addr, float v){
    if (v >= 0.0f) atomicMax((int*)addr, __float_as_int(v));
    else           atomicMin((unsigned int*)addr, __float_as_uint(v));
}

__device__ __forceinline__ void mma16816(float* d, const uint32_t* a,
                                         uint32_t b0, uint32_t b1){
    asm volatile("mma.sync.aligned.m16n8k16.row.col.f32.bf16.bf16.f32 "
        "{%0,%1,%2,%3}, {%4,%5,%6,%7}, {%8,%9}, {%0,%1,%2,%3};"
        : "+f"(d[0]), "+f"(d[1]), "+f"(d[2]), "+f"(d[3])
        : "r"(a[0]), "r"(a[1]), "r"(a[2]), "r"(a[3]), "r"(b0), "r"(b1));
}

// ---------------- K0: init row/col max scratch -------------------------------
__global__ void init_kernel(){
    int i = blockIdx.x*blockDim.x + threadIdx.x;
    if (i < BB*BB*LL){ g_rowmax[i] = -INFINITY; g_colmax[i] = -INFINITY; }
}

// ---------------- K1: QKV projection C = X @ W^T + b -------------------------
__global__ __launch_bounds__(256) void proj_kernel(
    const float* __restrict__ Xq, const float* __restrict__ Xk, const float* __restrict__ Xv,
    const float* __restrict__ Wq, const float* __restrict__ bq,
    const float* __restrict__ Wk, const float* __restrict__ bk,
    const float* __restrict__ Wv, const float* __restrict__ bv)
{
    int z = blockIdx.z;
    const float* X = (z==0)? Xq : (z==1)? Xk : Xv;
    const float* W = (z==0)? Wq : (z==1)? Wk : Wv;
    const float* bias = (z==0)? bq : (z==1)? bk : bv;
    float* dst = (z==0)? g_Q : (z==1)? g_K : g_V;
    __nv_bfloat16* dbf = (z==0)? g_Qbf : (z==1)? g_Kbf : (__nv_bfloat16*)0;

    __shared__ float As[16][68];
    __shared__ float Bs[16][68];

    int tid = threadIdx.x;
    int tx = tid & 15, ty = tid >> 4;
    int row0 = blockIdx.y * 64;
    int col0 = blockIdx.x * 64;

    float acc[4][4] = {};

    for (int k0 = 0; k0 < DD; k0 += 16){
        int m   = tid >> 2;
        int kk0 = (tid & 3) * 4;
        float4 va = *(const float4*)(X + (size_t)(row0 + m)*DD + k0 + kk0);
        As[kk0+0][m]=va.x; As[kk0+1][m]=va.y; As[kk0+2][m]=va.z; As[kk0+3][m]=va.w;
        float4 vb = *(const float4*)(W + (size_t)(col0 + m)*DD + k0 + kk0);
        Bs[kk0+0][m]=vb.x; Bs[kk0+1][m]=vb.y; Bs[kk0+2][m]=vb.z; Bs[kk0+3][m]=vb.w;
        __syncthreads();

        #pragma unroll
        for (int kk = 0; kk < 16; kk++){
            float4 a4 = *(const float4*)&As[kk][ty*4];
            float4 b4 = *(const float4*)&Bs[kk][tx*4];
            float a[4] = {a4.x,a4.y,a4.z,a4.w};
            float b[4] = {b4.x,b4.y,b4.z,b4.w};
            #pragma unroll
            for (int i=0;i<4;i++)
                #pragma unroll
                for (int j=0;j<4;j++)
                    acc[i][j] += a[i]*b[j];
        }
        __syncthreads();
    }

    #pragma unroll
    for (int i=0;i<4;i++){
        int r = row0 + ty*4 + i;
        #pragma unroll
        for (int j=0;j<4;j++){
            int c = col0 + tx*4 + j;
            float val = acc[i][j] + bias[c];
            dst[(size_t)r*DD + c] = val;
            if (z < 2) dbf[(size_t)r*DD + c] = __float2bfloat16(val);
        }
    }
}

// ---------------- K2: retrieval GEMM via mma.sync (bf16, fp32 accum) ---------
// Grid 4096 = 1024 pairs x 2 m-tiles(128) x 2 n-tiles(112).
// 8 warps = 4(M) x 2(N); warp tile 32 x 56 = 2 A-frags x 7 B-frags.
// KC=64 bf16 = 8 x uint4 PER ROW (R4/R5 only loaded 4 -> uninit smem -> NaN).
#define RT_NT  112
#define RT_STR 36          // uint32 per smem row (row data = 32 u32, +4 pad)

__global__ __launch_bounds__(256) void retrieve_mma(){
    __shared__ uint32_t As[128*RT_STR];
    __shared__ uint32_t Bs[RT_NT*RT_STR];
    __shared__ float s_rowred[128];
    __shared__ float s_colred[RT_NT];

    int tid = threadIdx.x;
    int lane = tid & 31, wid = tid >> 5;
    int g = lane >> 2, tg = lane & 3;
    int warpM = wid >> 1, warpN = wid & 1;

    int bx = blockIdx.x;
    int p = bx >> 2;                     // pair 0..1023
    int mtile = (bx >> 1) & 1;
    int ntile = bx & 1;
    int a = p >> 5, b = p & 31;
    int row0 = mtile * 128;
    int ncol0 = ntile * RT_NT;

    if (tid < 128)   s_rowred[tid] = -INFINITY;
    if (tid < RT_NT) s_colred[tid] = -INFINITY;

    const __nv_bfloat16* Abase = g_Qbf + (size_t)(a*LL)*DD;
    const __nv_bfloat16* Bbase = g_Kbf + (size_t)(b*LL)*DD;

    float acc[2][7][4];
    #pragma unroll
    for (int mf=0;mf<2;mf++)
        #pragma unroll
        for (int nf=0;nf<7;nf++)
            #pragma unroll
            for (int q=0;q<4;q++) acc[mf][nf][q] = 0.0f;

    for (int c = 0; c < 8; c++){
        int k0 = c * 64;
        // A: 128 rows x 8 uint4 (full 64 bf16 per row)
        for (int i = tid; i < 128*8; i += 256){
            int r = i >> 3, j = i & 7;
            int grow = row0 + r; if (grow > LL-1) grow = LL-1;
            uint4 v = ((const uint4*)(Abase + (size_t)grow*DD + k0))[j];
            *(uint4*)&As[r*RT_STR + j*4] = v;
        }
        // B: 112 rows x 8 uint4
        for (int i = tid; i < RT_NT*8; i += 256){
            int r = i >> 3, j = i & 7;
            int grow = ncol0 + r; if (grow > LL-1) grow = LL-1;
            uint4 v = ((const uint4*)(Bbase + (size_t)grow*DD + k0))[j];
            *(uint4*)&Bs[r*RT_STR + j*4] = v;
        }
        __syncthreads();

        #pragma unroll
        for (int ks = 0; ks < 4; ks++){
            uint32_t afr[2][4];
            #pragma unroll
            for (int mf=0; mf<2; mf++){
                int r = warpM*32 + mf*16 + g;
                const uint32_t* ap = &As[r*RT_STR + ks*8 + tg];
                afr[mf][0] = ap[0];
                afr[mf][1] = ap[8*RT_STR];
                afr[mf][2] = ap[4];
                afr[mf][3] = ap[8*RT_STR + 4];
            }
            #pragma unroll
            for (int nf = 0; nf < 7; nf++){
                int n = warpN*56 + nf*8 + g;
                const uint32_t* bp = &Bs[n*RT_STR + ks*8 + tg];
                uint32_t b0 = bp[0];
                uint32_t b1 = bp[4];
                mma16816(acc[0][nf], afr[0], b0, b1);
                mma16816(acc[1][nf], afr[1], b0, b1);
            }
        }
        __syncthreads();
    }

    // ---- epilogue: element-wise masked max via shared atomics ----
    #pragma unroll
    for (int mf = 0; mf < 2; mf++){
        int lr  = warpM*32 + mf*16 + g;     // local rows lr, lr+8
        int gr0 = row0 + lr;
        int gr8 = gr0 + 8;
        #pragma unroll
        for (int nf = 0; nf < 7; nf++){
            int lc = warpN*56 + nf*8 + tg*2;  // local cols lc, lc+1
            int gc = ncol0 + lc;
            float c0 = acc[mf][nf][0], c1 = acc[mf][nf][1];
            float c2 = acc[mf][nf][2], c3 = acc[mf][nf][3];
            bool cv0 = (gc < LL), cv1 = (gc+1 < LL);
            bool rv0 = (gr0 < LL), rv8 = (gr8 < LL);

            float rm0 = -INFINITY, rm8 = -INFINITY;
            if (cv0){ rm0 = fmaxf(rm0, c0); rm8 = fmaxf(rm8, c2); }
            if (cv1){ rm0 = fmaxf(rm0, c1); rm8 = fmaxf(rm8, c3); }
            atomicMaxF(&s_rowred[lr],     rm0);
            atomicMaxF(&s_rowred[lr + 8], rm8);

            float cm0 = -INFINITY, cm1 = -INFINITY;
            if (rv0){ cm0 = fmaxf(cm0, c0); cm1 = fmaxf(cm1, c1); }
            if (rv8){ cm0 = fmaxf(cm0, c2); cm1 = fmaxf(cm1, c3); }
            if (cv0) atomicMaxF(&s_colred[lc],     cm0);
            if (cv1) atomicMaxF(&s_colred[lc + 1], cm1);
        }
    }
    __syncthreads();

    if (tid < 128){
        int grow = row0 + tid;
        if (grow < LL) atomicMaxF(&g_rowmax[(size_t)p*LL + grow], s_rowred[tid]);
    }
    if (tid < RT_NT){
        int gcol = ncol0 + tid;
        if (gcol < LL) atomicMaxF(&g_colmax[(size_t)p*LL + gcol], s_colred[tid]);
    }
}

// ---------------- K3: logits reduce ------------------------------------------
__global__ __launch_bounds__(256) void logits_kernel(const float* __restrict__ ls,
                                                     float* __restrict__ out){
    int p = blockIdx.x;
    int t = threadIdx.x;
    float v = 0.0f;
    if (t < LL) v = g_rowmax[(size_t)p*LL + t] + g_colmax[(size_t)p*LL + t];
    #pragma unroll
    for (int o=16;o;o>>=1) v += __shfl_xor_sync(0xffffffffu, v, o);
    __shared__ float red[8];
    if ((t & 31) == 0) red[t >> 5] = v;
    __syncthreads();
    if (t == 0){
        float s = 0.0f;
        #pragma unroll
        for (int w=0; w<8; w++) s += red[w];
        out[p] = expf(ls[0]) * s / (2.0f * (float)LL);
    }
}

// ---------------- K4: self-attention per (b,h) -------------------------------
#define ATTN_SMEM ((196*65*2 + 8*64 + 8*200) * (int)sizeof(float))

__global__ __launch_bounds__(256) void attn_kernel(float* __restrict__ out_probs){
    int h = blockIdx.x, b = blockIdx.y;
    extern __shared__ float sm[];
    float* Ks  = sm;
    float* Vs  = sm + 196*65;
    float* qsh = sm + 196*65*2;
    float* psh = qsh + 8*64;

    int tid = threadIdx.x;
    int w = tid >> 5, lane = tid & 31;

    const float* Kg = g_K + (size_t)(b*LL)*DD + h*DHH;
    const float* Vg = g_V + (size_t)(b*LL)*DD + h*DHH;

    for (int i = tid; i < LL*16; i += 256){
        int m = i >> 4, d4 = (i & 15) * 4;
        float4 kv = *(const float4*)(Kg + (size_t)m*DD + d4);
        Ks[m*65+d4]=kv.x; Ks[m*65+d4+1]=kv.y; Ks[m*65+d4+2]=kv.z; Ks[m*65+d4+3]=kv.w;
        float4 vv = *(const float4*)(Vg + (size_t)m*DD + d4);
        Vs[m*65+d4]=vv.x; Vs[m*65+d4+1]=vv.y; Vs[m*65+d4+2]=vv.z; Vs[m*65+d4+3]=vv.w;
    }
    __syncthreads();

    float* qw = qsh + w*64;
    float* pw = psh + w*200;

    for (int l = w; l < LL; l += 8){
        const float* qrow = g_Q + (size_t)(b*LL + l)*DD + h*DHH;
        qw[lane]      = qrow[lane];
        qw[lane + 32] = qrow[lane + 32];
        __syncwarp();

        int mm[7]; bool valid[7];
        #pragma unroll
        for (int mi=0;mi<7;mi++){
            int m = lane + mi*32;
            valid[mi] = (m < LL);
            mm[mi] = valid[mi] ? m : (LL-1);
        }
        float s[7] = {};
        for (int d = 0; d < DHH; d++){
            float qd = qw[d];
            #pragma unroll
            for (int mi=0;mi<7;mi++)
                s[mi] += qd * Ks[mm[mi]*65 + d];
        }
        float mx = -INFINITY;
        #pragma unroll
        for (int mi=0;mi<7;mi++){
            s[mi] = valid[mi] ? s[mi]*0.125f : -INFINITY;
            mx = fmaxf(mx, s[mi]);
        }
        #pragma unroll
        for (int o=16;o;o>>=1) mx = fmaxf(mx, __shfl_xor_sync(0xffffffffu, mx, o));
        float sum = 0.0f;
        #pragma unroll
        for (int mi=0;mi<7;mi++){ float e = expf(s[mi]-mx); s[mi]=e; sum+=e; }
        #pragma unroll
        for (int o=16;o;o>>=1) sum += __shfl_xor_sync(0xffffffffu, sum, o);
        float inv = 1.0f / sum;

        float* pmrow = out_probs + (size_t)(b*LL + l)*LL;
        #pragma unroll
        for (int mi=0;mi<7;mi++){
            if (valid[mi]){
                float pv = s[mi]*inv;
                pw[mm[mi]] = pv;
                atomicAdd(&pmrow[mm[mi]], pv * 0.125f);
            }
        }
        __syncwarp();

        float c0 = 0.0f, c1 = 0.0f;
        for (int m = 0; m < LL; m++){
            float pm = pw[m];
            c0 += pm * Vs[m*65 + lane];
            c1 += pm * Vs[m*65 + 32 + lane];
        }
        float* crow = g_ctx + (size_t)(b*LL + l)*DD + h*DHH;
        crow[lane]      = c0;
        crow[lane + 32] = c1;
        __syncwarp();
    }
}

// ---------------- K5: residual + LayerNorm -----------------------------------
__global__ __launch_bounds__(128) void ln_kernel(const float* __restrict__ qin,
                                                 const float* __restrict__ gamma,
                                                 const float* __restrict__ beta,
                                                 float* __restrict__ out){
    int row = blockIdx.x;
    int t = threadIdx.x;
    const float* c = g_ctx + (size_t)row*DD;
    const float* q = qin   + (size_t)row*DD;
    __shared__ float red[4];

    float v[4]; float s = 0.0f;
    #pragma unroll
    for (int i=0;i<4;i++){ v[i] = c[t + i*128] + q[t + i*128]; s += v[i]; }
    #pragma unroll
    for (int o=16;o;o>>=1) s += __shfl_xor_sync(0xffffffffu, s, o);
    if ((t & 31) == 0) red[t>>5] = s;
    __syncthreads();
    float mu = (red[0]+red[1]+red[2]+red[3]) * (1.0f/DD);
    __syncthreads();

    float s2 = 0.0f;
    #pragma unroll
    for (int i=0;i<4;i++){ float d = v[i]-mu; s2 += d*d; }
    #pragma unroll
    for (int o=16;o;o>>=1) s2 += __shfl_xor_sync(0xffffffffu, s2, o);
    if ((t & 31) == 0) red[t>>5] = s2;
    __syncthreads();
    float var = (red[0]+red[1]+red[2]+red[3]) * (1.0f/DD);
    float invs = rsqrtf(var + 1e-6f);

    #pragma unroll
    for (int i=0;i<4;i++){
        int col = t + i*128;
        out[(size_t)row*DD + col] = (v[i]-mu)*invs*gamma[col] + beta[col];
    }
}

// ---------------- launch ------------------------------------------------------
extern "C" void kernel_launch(void* const* d_in, const int* in_sizes, int n_in,
                              void* d_out, int out_size)
{
    const float* q  = (const float*)d_in[0];
    const float* k  = (const float*)d_in[1];
    const float* v  = (const float*)d_in[2];
    const float* Wq = (const float*)d_in[3];
    const float* bq = (const float*)d_in[4];
    const float* Wk = (const float*)d_in[5];
    const float* bk = (const float*)d_in[6];
    const float* Wv = (const float*)d_in[7];
    const float* bv = (const float*)d_in[8];
    const float* gamma = (const float*)d_in[9];
    const float* beta  = (const float*)d_in[10];
    const float* ls    = (const float*)d_in[11];
    float* out = (float*)d_out;

    cudaFuncSetAttribute(attn_kernel, cudaFuncAttributeMaxDynamicSharedMemorySize, ATTN_SMEM);

    init_kernel<<<(BB*BB*LL + 255)/256, 256>>>();
    cudaMemsetAsync(out + OUT_PROBS, 0, (size_t)BB*LL*LL*sizeof(float));

    proj_kernel<<<dim3(DD/64, MM/64, 3), 256>>>(q, k, v, Wq, bq, Wk, bk, Wv, bv);

    retrieve_mma<<<4096, 256>>>();

    attn_kernel<<<dim3(HH, BB), 256, ATTN_SMEM>>>(out + OUT_PROBS);

    logits_kernel<<<BB*BB, 256>>>(ls, out + OUT_LOGITS);

    ln_kernel<<<MM, 128>>>(q, gamma, beta, out + OUT_CTX);
}

// round 8
// speedup vs baseline: 3.0192x; 1.2894x over previous
#include <cuda_runtime.h>
#include <cuda_bf16.h>
#include <math.h>
#include <stdint.h>

#define BB 32
#define LL 196
#define DD 512
#define HH 8
#define DHH 64
#define MM (BB*LL)              // 6272

// ---------------- scratch (static device allocations; no malloc) -------------
__device__ float g_Q[MM*DD];
__device__ float g_K[MM*DD];
__device__ float g_V[MM*DD];
__device__ float g_ctx[MM*DD];
__device__ __nv_bfloat16 g_Qbf[MM*DD];
__device__ __nv_bfloat16 g_Kbf[MM*DD];
__device__ float g_rowmax[BB*BB*LL];
__device__ float g_colmax[BB*BB*LL];

static const size_t OUT_CTX    = 0;
static const size_t OUT_LOGITS = (size_t)MM*DD;              // 3,211,264
static const size_t OUT_PROBS  = (size_t)MM*DD + BB*BB;      // 3,212,288

// float atomic max via signed/unsigned monotonicity trick (init = -inf)
__device__ __forceinline__ void atomicMaxF(float* addr, float v){
    if (v >= 0.0f) atomicMax((int*)addr, __float_as_int(v));
    else           atomicMin((unsigned int*)addr, __float_as_uint(v));
}

__device__ __forceinline__ void mma16816(float* d, const uint32_t* a,
                                         uint32_t b0, uint32_t b1){
    asm volatile("mma.sync.aligned.m16n8k16.row.col.f32.bf16.bf16.f32 "
        "{%0,%1,%2,%3}, {%4,%5,%6,%7}, {%8,%9}, {%0,%1,%2,%3};"
        : "+f"(d[0]), "+f"(d[1]), "+f"(d[2]), "+f"(d[3])
        : "r"(a[0]), "r"(a[1]), "r"(a[2]), "r"(a[3]), "r"(b0), "r"(b1));
}

__device__ __forceinline__ uint32_t packbf(__nv_bfloat16 a, __nv_bfloat16 b){
    __nv_bfloat162 t = __halves2bfloat162(a, b);
    return *(uint32_t*)&t;
}

// ---------------- K0: init row/col max scratch -------------------------------
__global__ void init_kernel(){
    int i = blockIdx.x*blockDim.x + threadIdx.x;
    if (i < BB*BB*LL){ g_rowmax[i] = -INFINITY; g_colmax[i] = -INFINITY; }
}

// ---------------- K1: QKV projection via bf16x3 split mma --------------------
// C = X @ W^T + b.  x*w ~= xh*wh + xh*wl + xl*wh  (xl*wl ~ 2^-16, dropped).
// CTA tile 128x128, KC=64. 8 warps = 4(M) x 2(N), warp tile 32x64.
#define PJ_STR 36                       // u32 per smem row (32 data + 4 pad)
#define PJ_TILE (128*PJ_STR)            // u32 per tile
#define PJ_SMEM (4*PJ_TILE*4)           // Ahi,Alo,Bhi,Blo  = 73728 B

__global__ __launch_bounds__(256) void proj_kernel(
    const float* __restrict__ Xq, const float* __restrict__ Xk, const float* __restrict__ Xv,
    const float* __restrict__ Wq, const float* __restrict__ bq,
    const float* __restrict__ Wk, const float* __restrict__ bk,
    const float* __restrict__ Wv, const float* __restrict__ bv)
{
    int z = blockIdx.z;
    const float* X = (z==0)? Xq : (z==1)? Xk : Xv;
    const float* W = (z==0)? Wq : (z==1)? Wk : Wv;
    const float* bias = (z==0)? bq : (z==1)? bk : bv;
    float* dst = (z==0)? g_Q : (z==1)? g_K : g_V;
    __nv_bfloat16* dbf = (z==0)? g_Qbf : (z==1)? g_Kbf : (__nv_bfloat16*)0;

    extern __shared__ uint32_t psm[];
    uint32_t* Ahi = psm;
    uint32_t* Alo = psm + PJ_TILE;
    uint32_t* Bhi = psm + 2*PJ_TILE;
    uint32_t* Blo = psm + 3*PJ_TILE;

    int tid = threadIdx.x;
    int lane = tid & 31, wid = tid >> 5;
    int g = lane >> 2, tg = lane & 3;
    int warpM = wid >> 1, warpN = wid & 1;

    int row0 = blockIdx.y * 128;
    int col0 = blockIdx.x * 128;

    float acc[2][8][4];
    #pragma unroll
    for (int mf=0;mf<2;mf++)
        #pragma unroll
        for (int nf=0;nf<8;nf++)
            #pragma unroll
            for (int q=0;q<4;q++) acc[mf][nf][q] = 0.0f;

    for (int c = 0; c < 8; c++){
        int k0 = c * 64;
        // stage X and W tiles, split hi/lo
        for (int i = tid; i < 128*16; i += 256){
            int r = i >> 4, j = i & 15;
            float4 f = *(const float4*)(X + (size_t)(row0 + r)*DD + k0 + j*4);
            __nv_bfloat16 hx = __float2bfloat16(f.x), hy = __float2bfloat16(f.y);
            __nv_bfloat16 hz = __float2bfloat16(f.z), hw = __float2bfloat16(f.w);
            Ahi[r*PJ_STR + j*2    ] = packbf(hx, hy);
            Ahi[r*PJ_STR + j*2 + 1] = packbf(hz, hw);
            Alo[r*PJ_STR + j*2    ] = packbf(__float2bfloat16(f.x - __bfloat162float(hx)),
                                             __float2bfloat16(f.y - __bfloat162float(hy)));
            Alo[r*PJ_STR + j*2 + 1] = packbf(__float2bfloat16(f.z - __bfloat162float(hz)),
                                             __float2bfloat16(f.w - __bfloat162float(hw)));
        }
        for (int i = tid; i < 128*16; i += 256){
            int r = i >> 4, j = i & 15;
            float4 f = *(const float4*)(W + (size_t)(col0 + r)*DD + k0 + j*4);
            __nv_bfloat16 hx = __float2bfloat16(f.x), hy = __float2bfloat16(f.y);
            __nv_bfloat16 hz = __float2bfloat16(f.z), hw = __float2bfloat16(f.w);
            Bhi[r*PJ_STR + j*2    ] = packbf(hx, hy);
            Bhi[r*PJ_STR + j*2 + 1] = packbf(hz, hw);
            Blo[r*PJ_STR + j*2    ] = packbf(__float2bfloat16(f.x - __bfloat162float(hx)),
                                             __float2bfloat16(f.y - __bfloat162float(hy)));
            Blo[r*PJ_STR + j*2 + 1] = packbf(__float2bfloat16(f.z - __bfloat162float(hz)),
                                             __float2bfloat16(f.w - __bfloat162float(hw)));
        }
        __syncthreads();

        #pragma unroll
        for (int ks = 0; ks < 4; ks++){
            uint32_t ahi[2][4], alo[2][4];
            #pragma unroll
            for (int mf=0; mf<2; mf++){
                int r = warpM*32 + mf*16 + g;
                const uint32_t* ah = &Ahi[r*PJ_STR + ks*8 + tg];
                ahi[mf][0] = ah[0]; ahi[mf][1] = ah[8*PJ_STR];
                ahi[mf][2] = ah[4]; ahi[mf][3] = ah[8*PJ_STR + 4];
                const uint32_t* al = &Alo[r*PJ_STR + ks*8 + tg];
                alo[mf][0] = al[0]; alo[mf][1] = al[8*PJ_STR];
                alo[mf][2] = al[4]; alo[mf][3] = al[8*PJ_STR + 4];
            }
            #pragma unroll
            for (int nf = 0; nf < 8; nf++){
                int n = warpN*64 + nf*8 + g;
                const uint32_t* bh = &Bhi[n*PJ_STR + ks*8 + tg];
                uint32_t bh0 = bh[0], bh1 = bh[4];
                const uint32_t* bl = &Blo[n*PJ_STR + ks*8 + tg];
                uint32_t bl0 = bl[0], bl1 = bl[4];
                #pragma unroll
                for (int mf=0; mf<2; mf++){
                    mma16816(acc[mf][nf], ahi[mf], bh0, bh1);
                    mma16816(acc[mf][nf], ahi[mf], bl0, bl1);
                    mma16816(acc[mf][nf], alo[mf], bh0, bh1);
                }
            }
        }
        __syncthreads();
    }

    #pragma unroll
    for (int mf = 0; mf < 2; mf++){
        int r0 = row0 + warpM*32 + mf*16 + g;
        #pragma unroll
        for (int nf = 0; nf < 8; nf++){
            int c0 = col0 + warpN*64 + nf*8 + tg*2;
            float b0 = bias[c0], b1 = bias[c0+1];
            float v00 = acc[mf][nf][0] + b0, v01 = acc[mf][nf][1] + b1;
            float v10 = acc[mf][nf][2] + b0, v11 = acc[mf][nf][3] + b1;
            dst[(size_t)r0*DD + c0]       = v00;
            dst[(size_t)r0*DD + c0 + 1]   = v01;
            dst[(size_t)(r0+8)*DD + c0]   = v10;
            dst[(size_t)(r0+8)*DD + c0+1] = v11;
            if (z < 2){
                dbf[(size_t)r0*DD + c0]       = __float2bfloat16(v00);
                dbf[(size_t)r0*DD + c0 + 1]   = __float2bfloat16(v01);
                dbf[(size_t)(r0+8)*DD + c0]   = __float2bfloat16(v10);
                dbf[(size_t)(r0+8)*DD + c0+1] = __float2bfloat16(v11);
            }
        }
    }
}

// ---------------- K2: retrieval GEMM via mma.sync (bf16, fp32 accum) ---------
#define RT_NT  112
#define RT_STR 36

__global__ __launch_bounds__(256) void retrieve_mma(){
    __shared__ uint32_t As[128*RT_STR];
    __shared__ uint32_t Bs[RT_NT*RT_STR];
    __shared__ float s_rowred[128];
    __shared__ float s_colred[RT_NT];

    int tid = threadIdx.x;
    int lane = tid & 31, wid = tid >> 5;
    int g = lane >> 2, tg = lane & 3;
    int warpM = wid >> 1, warpN = wid & 1;

    int bx = blockIdx.x;
    int p = bx >> 2;
    int mtile = (bx >> 1) & 1;
    int ntile = bx & 1;
    int a = p >> 5, b = p & 31;
    int row0 = mtile * 128;
    int ncol0 = ntile * RT_NT;

    if (tid < 128)   s_rowred[tid] = -INFINITY;
    if (tid < RT_NT) s_colred[tid] = -INFINITY;

    const __nv_bfloat16* Abase = g_Qbf + (size_t)(a*LL)*DD;
    const __nv_bfloat16* Bbase = g_Kbf + (size_t)(b*LL)*DD;

    float acc[2][7][4];
    #pragma unroll
    for (int mf=0;mf<2;mf++)
        #pragma unroll
        for (int nf=0;nf<7;nf++)
            #pragma unroll
            for (int q=0;q<4;q++) acc[mf][nf][q] = 0.0f;

    for (int c = 0; c < 8; c++){
        int k0 = c * 64;
        for (int i = tid; i < 128*8; i += 256){
            int r = i >> 3, j = i & 7;
            int grow = row0 + r; if (grow > LL-1) grow = LL-1;
            uint4 v = ((const uint4*)(Abase + (size_t)grow*DD + k0))[j];
            *(uint4*)&As[r*RT_STR + j*4] = v;
        }
        for (int i = tid; i < RT_NT*8; i += 256){
            int r = i >> 3, j = i & 7;
            int grow = ncol0 + r; if (grow > LL-1) grow = LL-1;
            uint4 v = ((const uint4*)(Bbase + (size_t)grow*DD + k0))[j];
            *(uint4*)&Bs[r*RT_STR + j*4] = v;
        }
        __syncthreads();

        #pragma unroll
        for (int ks = 0; ks < 4; ks++){
            uint32_t afr[2][4];
            #pragma unroll
            for (int mf=0; mf<2; mf++){
                int r = warpM*32 + mf*16 + g;
                const uint32_t* ap = &As[r*RT_STR + ks*8 + tg];
                afr[mf][0] = ap[0];
                afr[mf][1] = ap[8*RT_STR];
                afr[mf][2] = ap[4];
                afr[mf][3] = ap[8*RT_STR + 4];
            }
            #pragma unroll
            for (int nf = 0; nf < 7; nf++){
                int n = warpN*56 + nf*8 + g;
                const uint32_t* bp = &Bs[n*RT_STR + ks*8 + tg];
                uint32_t b0 = bp[0];
                uint32_t b1 = bp[4];
                mma16816(acc[0][nf], afr[0], b0, b1);
                mma16816(acc[1][nf], afr[1], b0, b1);
            }
        }
        __syncthreads();
    }

    #pragma unroll
    for (int mf = 0; mf < 2; mf++){
        int lr  = warpM*32 + mf*16 + g;
        int gr0 = row0 + lr;
        int gr8 = gr0 + 8;
        #pragma unroll
        for (int nf = 0; nf < 7; nf++){
            int lc = warpN*56 + nf*8 + tg*2;
            int gc = ncol0 + lc;
            float c0 = acc[mf][nf][0], c1 = acc[mf][nf][1];
            float c2 = acc[mf][nf][2], c3 = acc[mf][nf][3];
            bool cv0 = (gc < LL), cv1 = (gc+1 < LL);
            bool rv0 = (gr0 < LL), rv8 = (gr8 < LL);

            float rm0 = -INFINITY, rm8 = -INFINITY;
            if (cv0){ rm0 = fmaxf(rm0, c0); rm8 = fmaxf(rm8, c2); }
            if (cv1){ rm0 = fmaxf(rm0, c1); rm8 = fmaxf(rm8, c3); }
            atomicMaxF(&s_rowred[lr],     rm0);
            atomicMaxF(&s_rowred[lr + 8], rm8);

            float cm0 = -INFINITY, cm1 = -INFINITY;
            if (rv0){ cm0 = fmaxf(cm0, c0); cm1 = fmaxf(cm1, c1); }
            if (rv8){ cm0 = fmaxf(cm0, c2); cm1 = fmaxf(cm1, c3); }
            if (cv0) atomicMaxF(&s_colred[lc],     cm0);
            if (cv1) atomicMaxF(&s_colred[lc + 1], cm1);
        }
    }
    __syncthreads();

    if (tid < 128){
        int grow = row0 + tid;
        if (grow < LL) atomicMaxF(&g_rowmax[(size_t)p*LL + grow], s_rowred[tid]);
    }
    if (tid < RT_NT){
        int gcol = ncol0 + tid;
        if (gcol < LL) atomicMaxF(&g_colmax[(size_t)p*LL + gcol], s_colred[tid]);
    }
}

// ---------------- K3: logits reduce ------------------------------------------
__global__ __launch_bounds__(256) void logits_kernel(const float* __restrict__ ls,
                                                     float* __restrict__ out){
    int p = blockIdx.x;
    int t = threadIdx.x;
    float v = 0.0f;
    if (t < LL) v = g_rowmax[(size_t)p*LL + t] + g_colmax[(size_t)p*LL + t];
    #pragma unroll
    for (int o=16;o;o>>=1) v += __shfl_xor_sync(0xffffffffu, v, o);
    __shared__ float red[8];
    if ((t & 31) == 0) red[t >> 5] = v;
    __syncthreads();
    if (t == 0){
        float s = 0.0f;
        #pragma unroll
        for (int w=0; w<8; w++) s += red[w];
        out[p] = expf(ls[0]) * s / (2.0f * (float)LL);
    }
}

// ---------------- K4: self-attention, 4 query rows per warp ------------------
// smem: Ks[196][68] + Vs[196][64] + psh[8][2][200]  = 116,288 B  (2 CTAs/SM)
#define ATTN_SMEM ((196*68 + 196*64 + 8*2*200) * (int)sizeof(float))

__global__ __launch_bounds__(256, 2) void attn_kernel(float* __restrict__ out_probs){
    int h = blockIdx.x, b = blockIdx.y;
    extern __shared__ float sm[];
    float* Ks  = sm;                 // [196][68]
    float* Vs  = sm + 196*68;        // [196][64]
    float* psh = Vs + 196*64;        // [8][2][200]

    int tid = threadIdx.x;
    int w = tid >> 5, lane = tid & 31;

    const float* Kg = g_K + (size_t)(b*LL)*DD + h*DHH;
    const float* Vg = g_V + (size_t)(b*LL)*DD + h*DHH;

    for (int i = tid; i < LL*16; i += 256){
        int m = i >> 4, d4 = (i & 15) * 4;
        *(float4*)&Ks[m*68 + d4] = *(const float4*)(Kg + (size_t)m*DD + d4);
        *(float4*)&Vs[m*64 + d4] = *(const float4*)(Vg + (size_t)m*DD + d4);
    }
    __syncthreads();

    float* pw = psh + w*400;
    const float* Qb = g_Q + (size_t)(b*LL)*DD + h*DHH;

    int mm[7]; bool valid[7];
    #pragma unroll
    for (int mi=0;mi<7;mi++){
        int m = lane + mi*32;
        valid[mi] = (m < LL);
        mm[mi] = valid[mi] ? m : (LL-1);
    }

    for (int l0 = w*4; l0 < LL; l0 += 32){
        float s[4][7];
        #pragma unroll
        for (int li=0;li<4;li++)
            #pragma unroll
            for (int mi=0;mi<7;mi++) s[li][mi] = 0.0f;

        // ---- scores: 4 rows x 7 key-slots ----
        for (int d4 = 0; d4 < DHH; d4 += 4){
            float4 q0 = *(const float4*)(Qb + (size_t)(l0+0)*DD + d4);
            float4 q1 = *(const float4*)(Qb + (size_t)(l0+1)*DD + d4);
            float4 q2 = *(const float4*)(Qb + (size_t)(l0+2)*DD + d4);
            float4 q3 = *(const float4*)(Qb + (size_t)(l0+3)*DD + d4);
            #pragma unroll
            for (int mi=0;mi<7;mi++){
                float4 kf = *(const float4*)&Ks[mm[mi]*68 + d4];
                s[0][mi] += q0.x*kf.x + q0.y*kf.y + q0.z*kf.z + q0.w*kf.w;
                s[1][mi] += q1.x*kf.x + q1.y*kf.y + q1.z*kf.z + q1.w*kf.w;
                s[2][mi] += q2.x*kf.x + q2.y*kf.y + q2.z*kf.z + q2.w*kf.w;
                s[3][mi] += q3.x*kf.x + q3.y*kf.y + q3.z*kf.z + q3.w*kf.w;
            }
        }

        // ---- softmax per row + probs output ----
        #pragma unroll
        for (int li=0;li<4;li++){
            float mx = -INFINITY;
            #pragma unroll
            for (int mi=0;mi<7;mi++){
                s[li][mi] = valid[mi] ? s[li][mi]*0.125f : -INFINITY;
                mx = fmaxf(mx, s[li][mi]);
            }
            #pragma unroll
            for (int o=16;o;o>>=1) mx = fmaxf(mx, __shfl_xor_sync(0xffffffffu, mx, o));
            float sum = 0.0f;
            #pragma unroll
            for (int mi=0;mi<7;mi++){ float e = expf(s[li][mi]-mx); s[li][mi]=e; sum+=e; }
            #pragma unroll
            for (int o=16;o;o>>=1) sum += __shfl_xor_sync(0xffffffffu, sum, o);
            float inv = 1.0f / sum;

            float* pmrow = out_probs + (size_t)(b*LL + l0 + li)*LL;
            #pragma unroll
            for (int mi=0;mi<7;mi++){
                if (valid[mi]){
                    float pv = s[li][mi]*inv;
                    s[li][mi] = pv;
                    atomicAdd(&pmrow[mm[mi]], pv * 0.125f);
                }
            }
        }

        // ---- ctx rows in 2 pairs ----
        #pragma unroll
        for (int pi=0; pi<2; pi++){
            __syncwarp();
            #pragma unroll
            for (int mi=0;mi<7;mi++){
                if (valid[mi]){
                    pw[mm[mi]]       = s[2*pi][mi];
                    pw[200 + mm[mi]] = s[2*pi+1][mi];
                }
            }
            __syncwarp();
            float c00=0.f,c01=0.f,c10=0.f,c11=0.f;
            for (int m = 0; m < LL; m++){
                float2 v2 = *(const float2*)&Vs[m*64 + lane*2];
                float p0 = pw[m], p1 = pw[200 + m];
                c00 += p0*v2.x; c01 += p0*v2.y;
                c10 += p1*v2.x; c11 += p1*v2.y;
            }
            float* cr0 = g_ctx + (size_t)(b*LL + l0 + 2*pi)*DD + h*DHH + lane*2;
            float* cr1 = cr0 + DD;
            cr0[0] = c00; cr0[1] = c01;
            cr1[0] = c10; cr1[1] = c11;
        }
    }
}

// ---------------- K5: residual + LayerNorm -----------------------------------
__global__ __launch_bounds__(128) void ln_kernel(const float* __restrict__ qin,
                                                 const float* __restrict__ gamma,
                                                 const float* __restrict__ beta,
                                                 float* __restrict__ out){
    int row = blockIdx.x;
    int t = threadIdx.x;
    const float* c = g_ctx + (size_t)row*DD;
    const float* q = qin   + (size_t)row*DD;
    __shared__ float red[4];

    float v[4]; float s = 0.0f;
    #pragma unroll
    for (int i=0;i<4;i++){ v[i] = c[t + i*128] + q[t + i*128]; s += v[i]; }
    #pragma unroll
    for (int o=16;o;o>>=1) s += __shfl_xor_sync(0xffffffffu, s, o);
    if ((t & 31) == 0) red[t>>5] = s;
    __syncthreads();
    float mu = (red[0]+red[1]+red[2]+red[3]) * (1.0f/DD);
    __syncthreads();

    float s2 = 0.0f;
    #pragma unroll
    for (int i=0;i<4;i++){ float d = v[i]-mu; s2 += d*d; }
    #pragma unroll
    for (int o=16;o;o>>=1) s2 += __shfl_xor_sync(0xffffffffu, s2, o);
    if ((t & 31) == 0) red[t>>5] = s2;
    __syncthreads();
    float var = (red[0]+red[1]+red[2]+red[3]) * (1.0f/DD);
    float invs = rsqrtf(var + 1e-6f);

    #pragma unroll
    for (int i=0;i<4;i++){
        int col = t + i*128;
        out[(size_t)row*DD + col] = (v[i]-mu)*invs*gamma[col] + beta[col];
    }
}

// ---------------- launch ------------------------------------------------------
extern "C" void kernel_launch(void* const* d_in, const int* in_sizes, int n_in,
                              void* d_out, int out_size)
{
    const float* q  = (const float*)d_in[0];
    const float* k  = (const float*)d_in[1];
    const float* v  = (const float*)d_in[2];
    const float* Wq = (const float*)d_in[3];
    const float* bq = (const float*)d_in[4];
    const float* Wk = (const float*)d_in[5];
    const float* bk = (const float*)d_in[6];
    const float* Wv = (const float*)d_in[7];
    const float* bv = (const float*)d_in[8];
    const float* gamma = (const float*)d_in[9];
    const float* beta  = (const float*)d_in[10];
    const float* ls    = (const float*)d_in[11];
    float* out = (float*)d_out;

    cudaFuncSetAttribute(attn_kernel, cudaFuncAttributeMaxDynamicSharedMemorySize, ATTN_SMEM);
    cudaFuncSetAttribute(proj_kernel, cudaFuncAttributeMaxDynamicSharedMemorySize, PJ_SMEM);

    init_kernel<<<(BB*BB*LL + 255)/256, 256>>>();
    cudaMemsetAsync(out + OUT_PROBS, 0, (size_t)BB*LL*LL*sizeof(float));

    proj_kernel<<<dim3(4, 49, 3), 256, PJ_SMEM>>>(q, k, v, Wq, bq, Wk, bk, Wv, bv);

    retrieve_mma<<<4096, 256>>>();

    attn_kernel<<<dim3(HH, BB), 256, ATTN_SMEM>>>(out + OUT_PROBS);

    logits_kernel<<<BB*BB, 256>>>(ls, out + OUT_LOGITS);

    ln_kernel<<<MM, 128>>>(q, gamma, beta, out + OUT_CTX);
}

// round 9
// speedup vs baseline: 3.2270x; 1.0688x over previous
#include <cuda_runtime.h>
#include <cuda_bf16.h>
#include <math.h>
#include <stdint.h>

#define BB 32
#define LL 196
#define DD 512
#define HH 8
#define DHH 64
#define MM (BB*LL)              // 6272

// ---------------- scratch (static device allocations; no malloc) -------------
__device__ float g_Q[MM*DD];
__device__ float g_K[MM*DD];
__device__ float g_V[MM*DD];
__device__ float g_ctx[MM*DD];
__device__ __nv_bfloat16 g_Qbf[MM*DD];
__device__ __nv_bfloat16 g_Kbf[MM*DD];
__device__ float g_rowmax[BB*BB*LL];
__device__ float g_colmax[BB*BB*LL];
// pre-split bf16 operands for the projection GEMM
__device__ __nv_bfloat16 g_Xhi[3*MM*DD];
__device__ __nv_bfloat16 g_Xlo[3*MM*DD];
__device__ __nv_bfloat16 g_Whi[3*DD*DD];
__device__ __nv_bfloat16 g_Wlo[3*DD*DD];

static const size_t OUT_CTX    = 0;
static const size_t OUT_LOGITS = (size_t)MM*DD;              // 3,211,264
static const size_t OUT_PROBS  = (size_t)MM*DD + BB*BB;      // 3,212,288

// float atomic max via signed/unsigned monotonicity trick (init = -inf)
__device__ __forceinline__ void atomicMaxF(float* addr, float v){
    if (v >= 0.0f) atomicMax((int*)addr, __float_as_int(v));
    else           atomicMin((unsigned int*)addr, __float_as_uint(v));
}

__device__ __forceinline__ void mma16816(float* d, const uint32_t* a,
                                         uint32_t b0, uint32_t b1){
    asm volatile("mma.sync.aligned.m16n8k16.row.col.f32.bf16.bf16.f32 "
        "{%0,%1,%2,%3}, {%4,%5,%6,%7}, {%8,%9}, {%0,%1,%2,%3};"
        : "+f"(d[0]), "+f"(d[1]), "+f"(d[2]), "+f"(d[3])
        : "r"(a[0]), "r"(a[1]), "r"(a[2]), "r"(a[3]), "r"(b0), "r"(b1));
}

__device__ __forceinline__ uint32_t packbf(__nv_bfloat16 a, __nv_bfloat16 b){
    __nv_bfloat162 t = __halves2bfloat162(a, b);
    return *(uint32_t*)&t;
}

// ---------------- K0: init row/col max scratch -------------------------------
__global__ void init_kernel(){
    int i = blockIdx.x*blockDim.x + threadIdx.x;
    if (i < BB*BB*LL){ g_rowmax[i] = -INFINITY; g_colmax[i] = -INFINITY; }
}

// ---------------- K0b: fp32 -> bf16 hi/lo split (X and W) --------------------
__global__ __launch_bounds__(256) void split_x_kernel(
    const float* __restrict__ Xq, const float* __restrict__ Xk, const float* __restrict__ Xv){
    int z = blockIdx.z;
    const float* src = (z==0)? Xq : (z==1)? Xk : Xv;
    __nv_bfloat16* hi = g_Xhi + (size_t)z*MM*DD;
    __nv_bfloat16* lo = g_Xlo + (size_t)z*MM*DD;
    size_t i = ((size_t)blockIdx.x*256 + threadIdx.x)*4;
    if (i < (size_t)MM*DD){
        float4 f = *(const float4*)(src + i);
        __nv_bfloat16 hx=__float2bfloat16(f.x), hy=__float2bfloat16(f.y);
        __nv_bfloat16 hz=__float2bfloat16(f.z), hw=__float2bfloat16(f.w);
        uint2 vh; vh.x = packbf(hx,hy); vh.y = packbf(hz,hw);
        *(uint2*)(hi + i) = vh;
        uint2 vl;
        vl.x = packbf(__float2bfloat16(f.x-__bfloat162float(hx)),
                      __float2bfloat16(f.y-__bfloat162float(hy)));
        vl.y = packbf(__float2bfloat16(f.z-__bfloat162float(hz)),
                      __float2bfloat16(f.w-__bfloat162float(hw)));
        *(uint2*)(lo + i) = vl;
    }
}

__global__ __launch_bounds__(256) void split_w_kernel(
    const float* __restrict__ Wq, const float* __restrict__ Wk, const float* __restrict__ Wv){
    int z = blockIdx.z;
    const float* src = (z==0)? Wq : (z==1)? Wk : Wv;
    __nv_bfloat16* hi = g_Whi + (size_t)z*DD*DD;
    __nv_bfloat16* lo = g_Wlo + (size_t)z*DD*DD;
    size_t i = ((size_t)blockIdx.x*256 + threadIdx.x)*4;
    if (i < (size_t)DD*DD){
        float4 f = *(const float4*)(src + i);
        __nv_bfloat16 hx=__float2bfloat16(f.x), hy=__float2bfloat16(f.y);
        __nv_bfloat16 hz=__float2bfloat16(f.z), hw=__float2bfloat16(f.w);
        uint2 vh; vh.x = packbf(hx,hy); vh.y = packbf(hz,hw);
        *(uint2*)(hi + i) = vh;
        uint2 vl;
        vl.x = packbf(__float2bfloat16(f.x-__bfloat162float(hx)),
                      __float2bfloat16(f.y-__bfloat162float(hy)));
        vl.y = packbf(__float2bfloat16(f.z-__bfloat162float(hz)),
                      __float2bfloat16(f.w-__bfloat162float(hw)));
        *(uint2*)(lo + i) = vl;
    }
}

// ---------------- K1: QKV projection via bf16x3 split mma --------------------
// C = X @ W^T + b.  x*w ~= xh*wh + xh*wl + xl*wh.  Operands pre-split.
#define PJ_STR 36
#define PJ_TILE (128*PJ_STR)
#define PJ_SMEM (4*PJ_TILE*4)           // 73728 B

__global__ __launch_bounds__(256) void proj_kernel(
    const float* __restrict__ bq, const float* __restrict__ bk, const float* __restrict__ bv)
{
    int z = blockIdx.z;
    const float* bias = (z==0)? bq : (z==1)? bk : bv;
    float* dst = (z==0)? g_Q : (z==1)? g_K : g_V;
    __nv_bfloat16* dbf = (z==0)? g_Qbf : (z==1)? g_Kbf : (__nv_bfloat16*)0;
    const __nv_bfloat16* Xh = g_Xhi + (size_t)z*MM*DD;
    const __nv_bfloat16* Xl = g_Xlo + (size_t)z*MM*DD;
    const __nv_bfloat16* Wh = g_Whi + (size_t)z*DD*DD;
    const __nv_bfloat16* Wl = g_Wlo + (size_t)z*DD*DD;

    extern __shared__ uint32_t psm[];
    uint32_t* Ahi = psm;
    uint32_t* Alo = psm + PJ_TILE;
    uint32_t* Bhi = psm + 2*PJ_TILE;
    uint32_t* Blo = psm + 3*PJ_TILE;

    int tid = threadIdx.x;
    int lane = tid & 31, wid = tid >> 5;
    int g = lane >> 2, tg = lane & 3;
    int warpM = wid >> 1, warpN = wid & 1;

    int row0 = blockIdx.y * 128;
    int col0 = blockIdx.x * 128;

    float acc[2][8][4];
    #pragma unroll
    for (int mf=0;mf<2;mf++)
        #pragma unroll
        for (int nf=0;nf<8;nf++)
            #pragma unroll
            for (int q=0;q<4;q++) acc[mf][nf][q] = 0.0f;

    for (int c = 0; c < 8; c++){
        int k0 = c * 64;
        for (int i = tid; i < 128*8; i += 256){
            int r = i >> 3, j = i & 7;
            *(uint4*)&Ahi[r*PJ_STR + j*4] = ((const uint4*)(Xh + (size_t)(row0+r)*DD + k0))[j];
            *(uint4*)&Alo[r*PJ_STR + j*4] = ((const uint4*)(Xl + (size_t)(row0+r)*DD + k0))[j];
        }
        for (int i = tid; i < 128*8; i += 256){
            int r = i >> 3, j = i & 7;
            *(uint4*)&Bhi[r*PJ_STR + j*4] = ((const uint4*)(Wh + (size_t)(col0+r)*DD + k0))[j];
            *(uint4*)&Blo[r*PJ_STR + j*4] = ((const uint4*)(Wl + (size_t)(col0+r)*DD + k0))[j];
        }
        __syncthreads();

        #pragma unroll
        for (int ks = 0; ks < 4; ks++){
            uint32_t ahi[2][4], alo[2][4];
            #pragma unroll
            for (int mf=0; mf<2; mf++){
                int r = warpM*32 + mf*16 + g;
                const uint32_t* ah = &Ahi[r*PJ_STR + ks*8 + tg];
                ahi[mf][0] = ah[0]; ahi[mf][1] = ah[8*PJ_STR];
                ahi[mf][2] = ah[4]; ahi[mf][3] = ah[8*PJ_STR + 4];
                const uint32_t* al = &Alo[r*PJ_STR + ks*8 + tg];
                alo[mf][0] = al[0]; alo[mf][1] = al[8*PJ_STR];
                alo[mf][2] = al[4]; alo[mf][3] = al[8*PJ_STR + 4];
            }
            #pragma unroll
            for (int nf = 0; nf < 8; nf++){
                int n = warpN*64 + nf*8 + g;
                const uint32_t* bh = &Bhi[n*PJ_STR + ks*8 + tg];
                uint32_t bh0 = bh[0], bh1 = bh[4];
                const uint32_t* bl = &Blo[n*PJ_STR + ks*8 + tg];
                uint32_t bl0 = bl[0], bl1 = bl[4];
                #pragma unroll
                for (int mf=0; mf<2; mf++){
                    mma16816(acc[mf][nf], ahi[mf], bh0, bh1);
                    mma16816(acc[mf][nf], ahi[mf], bl0, bl1);
                    mma16816(acc[mf][nf], alo[mf], bh0, bh1);
                }
            }
        }
        __syncthreads();
    }

    #pragma unroll
    for (int mf = 0; mf < 2; mf++){
        int r0 = row0 + warpM*32 + mf*16 + g;
        #pragma unroll
        for (int nf = 0; nf < 8; nf++){
            int c0 = col0 + warpN*64 + nf*8 + tg*2;
            float b0 = bias[c0], b1 = bias[c0+1];
            float v00 = acc[mf][nf][0] + b0, v01 = acc[mf][nf][1] + b1;
            float v10 = acc[mf][nf][2] + b0, v11 = acc[mf][nf][3] + b1;
            dst[(size_t)r0*DD + c0]       = v00;
            dst[(size_t)r0*DD + c0 + 1]   = v01;
            dst[(size_t)(r0+8)*DD + c0]   = v10;
            dst[(size_t)(r0+8)*DD + c0+1] = v11;
            if (z < 2){
                dbf[(size_t)r0*DD + c0]       = __float2bfloat16(v00);
                dbf[(size_t)r0*DD + c0 + 1]   = __float2bfloat16(v01);
                dbf[(size_t)(r0+8)*DD + c0]   = __float2bfloat16(v10);
                dbf[(size_t)(r0+8)*DD + c0+1] = __float2bfloat16(v11);
            }
        }
    }
}

// ---------------- K2: retrieval GEMM via mma.sync (bf16, fp32 accum) ---------
#define RT_NT  112
#define RT_STR 36

__global__ __launch_bounds__(256) void retrieve_mma(){
    __shared__ uint32_t As[128*RT_STR];
    __shared__ uint32_t Bs[RT_NT*RT_STR];
    __shared__ float s_rowred[128];
    __shared__ float s_colred[RT_NT];

    int tid = threadIdx.x;
    int lane = tid & 31, wid = tid >> 5;
    int g = lane >> 2, tg = lane & 3;
    int warpM = wid >> 1, warpN = wid & 1;

    int bx = blockIdx.x;
    int p = bx >> 2;
    int mtile = (bx >> 1) & 1;
    int ntile = bx & 1;
    int a = p >> 5, b = p & 31;
    int row0 = mtile * 128;
    int ncol0 = ntile * RT_NT;

    if (tid < 128)   s_rowred[tid] = -INFINITY;
    if (tid < RT_NT) s_colred[tid] = -INFINITY;

    const __nv_bfloat16* Abase = g_Qbf + (size_t)(a*LL)*DD;
    const __nv_bfloat16* Bbase = g_Kbf + (size_t)(b*LL)*DD;

    float acc[2][7][4];
    #pragma unroll
    for (int mf=0;mf<2;mf++)
        #pragma unroll
        for (int nf=0;nf<7;nf++)
            #pragma unroll
            for (int q=0;q<4;q++) acc[mf][nf][q] = 0.0f;

    for (int c = 0; c < 8; c++){
        int k0 = c * 64;
        for (int i = tid; i < 128*8; i += 256){
            int r = i >> 3, j = i & 7;
            int grow = row0 + r; if (grow > LL-1) grow = LL-1;
            uint4 v = ((const uint4*)(Abase + (size_t)grow*DD + k0))[j];
            *(uint4*)&As[r*RT_STR + j*4] = v;
        }
        for (int i = tid; i < RT_NT*8; i += 256){
            int r = i >> 3, j = i & 7;
            int grow = ncol0 + r; if (grow > LL-1) grow = LL-1;
            uint4 v = ((const uint4*)(Bbase + (size_t)grow*DD + k0))[j];
            *(uint4*)&Bs[r*RT_STR + j*4] = v;
        }
        __syncthreads();

        #pragma unroll
        for (int ks = 0; ks < 4; ks++){
            uint32_t afr[2][4];
            #pragma unroll
            for (int mf=0; mf<2; mf++){
                int r = warpM*32 + mf*16 + g;
                const uint32_t* ap = &As[r*RT_STR + ks*8 + tg];
                afr[mf][0] = ap[0];
                afr[mf][1] = ap[8*RT_STR];
                afr[mf][2] = ap[4];
                afr[mf][3] = ap[8*RT_STR + 4];
            }
            #pragma unroll
            for (int nf = 0; nf < 7; nf++){
                int n = warpN*56 + nf*8 + g;
                const uint32_t* bp = &Bs[n*RT_STR + ks*8 + tg];
                uint32_t b0 = bp[0];
                uint32_t b1 = bp[4];
                mma16816(acc[0][nf], afr[0], b0, b1);
                mma16816(acc[1][nf], afr[1], b0, b1);
            }
        }
        __syncthreads();
    }

    #pragma unroll
    for (int mf = 0; mf < 2; mf++){
        int lr  = warpM*32 + mf*16 + g;
        int gr0 = row0 + lr;
        int gr8 = gr0 + 8;
        #pragma unroll
        for (int nf = 0; nf < 7; nf++){
            int lc = warpN*56 + nf*8 + tg*2;
            int gc = ncol0 + lc;
            float c0 = acc[mf][nf][0], c1 = acc[mf][nf][1];
            float c2 = acc[mf][nf][2], c3 = acc[mf][nf][3];
            bool cv0 = (gc < LL), cv1 = (gc+1 < LL);
            bool rv0 = (gr0 < LL), rv8 = (gr8 < LL);

            float rm0 = -INFINITY, rm8 = -INFINITY;
            if (cv0){ rm0 = fmaxf(rm0, c0); rm8 = fmaxf(rm8, c2); }
            if (cv1){ rm0 = fmaxf(rm0, c1); rm8 = fmaxf(rm8, c3); }
            atomicMaxF(&s_rowred[lr],     rm0);
            atomicMaxF(&s_rowred[lr + 8], rm8);

            float cm0 = -INFINITY, cm1 = -INFINITY;
            if (rv0){ cm0 = fmaxf(cm0, c0); cm1 = fmaxf(cm1, c1); }
            if (rv8){ cm0 = fmaxf(cm0, c2); cm1 = fmaxf(cm1, c3); }
            if (cv0) atomicMaxF(&s_colred[lc],     cm0);
            if (cv1) atomicMaxF(&s_colred[lc + 1], cm1);
        }
    }
    __syncthreads();

    if (tid < 128){
        int grow = row0 + tid;
        if (grow < LL) atomicMaxF(&g_rowmax[(size_t)p*LL + grow], s_rowred[tid]);
    }
    if (tid < RT_NT){
        int gcol = ncol0 + tid;
        if (gcol < LL) atomicMaxF(&g_colmax[(size_t)p*LL + gcol], s_colred[tid]);
    }
}

// ---------------- K3: logits reduce ------------------------------------------
__global__ __launch_bounds__(256) void logits_kernel(const float* __restrict__ ls,
                                                     float* __restrict__ out){
    int p = blockIdx.x;
    int t = threadIdx.x;
    float v = 0.0f;
    if (t < LL) v = g_rowmax[(size_t)p*LL + t] + g_colmax[(size_t)p*LL + t];
    #pragma unroll
    for (int o=16;o;o>>=1) v += __shfl_xor_sync(0xffffffffu, v, o);
    __shared__ float red[8];
    if ((t & 31) == 0) red[t >> 5] = v;
    __syncthreads();
    if (t == 0){
        float s = 0.0f;
        #pragma unroll
        for (int w=0; w<8; w++) s += red[w];
        out[p] = expf(ls[0]) * s / (2.0f * (float)LL);
    }
}

// ---------------- K4: self-attention, 4 rows/warp, shuffle-P ctx -------------
// smem: Ks[196][68] + Vs[196][64] = 103,488 B  -> 2 CTAs/SM
#define ATTN_SMEM ((196*68 + 196*64) * (int)sizeof(float))

__global__ __launch_bounds__(256, 2) void attn_kernel(float* __restrict__ out_probs){
    int h = blockIdx.x, b = blockIdx.y;
    extern __shared__ float sm[];
    float* Ks  = sm;                 // [196][68]
    float* Vs  = sm + 196*68;        // [196][64]

    int tid = threadIdx.x;
    int w = tid >> 5, lane = tid & 31;

    const float* Kg = g_K + (size_t)(b*LL)*DD + h*DHH;
    const float* Vg = g_V + (size_t)(b*LL)*DD + h*DHH;

    for (int i = tid; i < LL*16; i += 256){
        int m = i >> 4, d4 = (i & 15) * 4;
        *(float4*)&Ks[m*68 + d4] = *(const float4*)(Kg + (size_t)m*DD + d4);
        *(float4*)&Vs[m*64 + d4] = *(const float4*)(Vg + (size_t)m*DD + d4);
    }
    __syncthreads();

    const float* Qb = g_Q + (size_t)(b*LL)*DD + h*DHH;

    int mm[7]; bool valid[7];
    #pragma unroll
    for (int mi=0;mi<7;mi++){
        int m = lane + mi*32;
        valid[mi] = (m < LL);
        mm[mi] = valid[mi] ? m : (LL-1);
    }

    for (int l0 = w*4; l0 < LL; l0 += 32){
        float s[4][7];
        #pragma unroll
        for (int li=0;li<4;li++)
            #pragma unroll
            for (int mi=0;mi<7;mi++) s[li][mi] = 0.0f;

        // ---- scores ----
        for (int d4 = 0; d4 < DHH; d4 += 4){
            float4 q0 = *(const float4*)(Qb + (size_t)(l0+0)*DD + d4);
            float4 q1 = *(const float4*)(Qb + (size_t)(l0+1)*DD + d4);
            float4 q2 = *(const float4*)(Qb + (size_t)(l0+2)*DD + d4);
            float4 q3 = *(const float4*)(Qb + (size_t)(l0+3)*DD + d4);
            #pragma unroll
            for (int mi=0;mi<7;mi++){
                float4 kf = *(const float4*)&Ks[mm[mi]*68 + d4];
                s[0][mi] += q0.x*kf.x + q0.y*kf.y + q0.z*kf.z + q0.w*kf.w;
                s[1][mi] += q1.x*kf.x + q1.y*kf.y + q1.z*kf.z + q1.w*kf.w;
                s[2][mi] += q2.x*kf.x + q2.y*kf.y + q2.z*kf.z + q2.w*kf.w;
                s[3][mi] += q3.x*kf.x + q3.y*kf.y + q3.z*kf.z + q3.w*kf.w;
            }
        }

        // ---- softmax per row + probs output (invalid slots -> p = 0) ----
        #pragma unroll
        for (int li=0;li<4;li++){
            float mx = -INFINITY;
            #pragma unroll
            for (int mi=0;mi<7;mi++){
                s[li][mi] = valid[mi] ? s[li][mi]*0.125f : -INFINITY;
                mx = fmaxf(mx, s[li][mi]);
            }
            #pragma unroll
            for (int o=16;o;o>>=1) mx = fmaxf(mx, __shfl_xor_sync(0xffffffffu, mx, o));
            float sum = 0.0f;
            #pragma unroll
            for (int mi=0;mi<7;mi++){ float e = expf(s[li][mi]-mx); s[li][mi]=e; sum+=e; }
            #pragma unroll
            for (int o=16;o;o>>=1) sum += __shfl_xor_sync(0xffffffffu, sum, o);
            float inv = 1.0f / sum;

            float* pmrow = out_probs + (size_t)(b*LL + l0 + li)*LL;
            #pragma unroll
            for (int mi=0;mi<7;mi++){
                s[li][mi] *= inv;                       // 0 stays 0 for invalid
                if (valid[mi]) atomicAdd(&pmrow[mm[mi]], s[li][mi] * 0.125f);
            }
        }

        // ---- ctx: broadcast p via shuffle, accumulate V ----
        float c0x=0.f,c0y=0.f,c1x=0.f,c1y=0.f,c2x=0.f,c2y=0.f,c3x=0.f,c3y=0.f;
        for (int mi=0;mi<7;mi++){
            float p0r = s[0][mi], p1r = s[1][mi], p2r = s[2][mi], p3r = s[3][mi];
            #pragma unroll
            for (int ls=0; ls<32; ls++){
                int m = mi*32 + ls;                     // uniform across warp
                float p0 = __shfl_sync(0xffffffffu, p0r, ls);
                float p1 = __shfl_sync(0xffffffffu, p1r, ls);
                float p2 = __shfl_sync(0xffffffffu, p2r, ls);
                float p3 = __shfl_sync(0xffffffffu, p3r, ls);
                if (m < LL){
                    float2 v2 = *(const float2*)&Vs[m*64 + lane*2];
                    c0x += p0*v2.x; c0y += p0*v2.y;
                    c1x += p1*v2.x; c1y += p1*v2.y;
                    c2x += p2*v2.x; c2y += p2*v2.y;
                    c3x += p3*v2.x; c3y += p3*v2.y;
                }
            }
        }
        float* cr = g_ctx + (size_t)(b*LL + l0)*DD + h*DHH + lane*2;
        cr[0]      = c0x; cr[1]      = c0y;
        cr[DD]     = c1x; cr[DD+1]   = c1y;
        cr[2*DD]   = c2x; cr[2*DD+1] = c2y;
        cr[3*DD]   = c3x; cr[3*DD+1] = c3y;
    }
}

// ---------------- K5: residual + LayerNorm -----------------------------------
__global__ __launch_bounds__(128) void ln_kernel(const float* __restrict__ qin,
                                                 const float* __restrict__ gamma,
                                                 const float* __restrict__ beta,
                                                 float* __restrict__ out){
    int row = blockIdx.x;
    int t = threadIdx.x;
    const float* c = g_ctx + (size_t)row*DD;
    const float* q = qin   + (size_t)row*DD;
    __shared__ float red[4];

    float v[4]; float s = 0.0f;
    #pragma unroll
    for (int i=0;i<4;i++){ v[i] = c[t + i*128] + q[t + i*128]; s += v[i]; }
    #pragma unroll
    for (int o=16;o;o>>=1) s += __shfl_xor_sync(0xffffffffu, s, o);
    if ((t & 31) == 0) red[t>>5] = s;
    __syncthreads();
    float mu = (red[0]+red[1]+red[2]+red[3]) * (1.0f/DD);
    __syncthreads();

    float s2 = 0.0f;
    #pragma unroll
    for (int i=0;i<4;i++){ float d = v[i]-mu; s2 += d*d; }
    #pragma unroll
    for (int o=16;o;o>>=1) s2 += __shfl_xor_sync(0xffffffffu, s2, o);
    if ((t & 31) == 0) red[t>>5] = s2;
    __syncthreads();
    float var = (red[0]+red[1]+red[2]+red[3]) * (1.0f/DD);
    float invs = rsqrtf(var + 1e-6f);

    #pragma unroll
    for (int i=0;i<4;i++){
        int col = t + i*128;
        out[(size_t)row*DD + col] = (v[i]-mu)*invs*gamma[col] + beta[col];
    }
}

// ---------------- launch ------------------------------------------------------
extern "C" void kernel_launch(void* const* d_in, const int* in_sizes, int n_in,
                              void* d_out, int out_size)
{
    const float* q  = (const float*)d_in[0];
    const float* k  = (const float*)d_in[1];
    const float* v  = (const float*)d_in[2];
    const float* Wq = (const float*)d_in[3];
    const float* bq = (const float*)d_in[4];
    const float* Wk = (const float*)d_in[5];
    const float* bk = (const float*)d_in[6];
    const float* Wv = (const float*)d_in[7];
    const float* bv = (const float*)d_in[8];
    const float* gamma = (const float*)d_in[9];
    const float* beta  = (const float*)d_in[10];
    const float* ls    = (const float*)d_in[11];
    float* out = (float*)d_out;

    cudaFuncSetAttribute(attn_kernel, cudaFuncAttributeMaxDynamicSharedMemorySize, ATTN_SMEM);
    cudaFuncSetAttribute(proj_kernel, cudaFuncAttributeMaxDynamicSharedMemorySize, PJ_SMEM);

    init_kernel<<<(BB*BB*LL + 255)/256, 256>>>();
    cudaMemsetAsync(out + OUT_PROBS, 0, (size_t)BB*LL*LL*sizeof(float));

    split_x_kernel<<<dim3((MM*DD/4 + 255)/256, 1, 3), 256>>>(q, k, v);
    split_w_kernel<<<dim3((DD*DD/4 + 255)/256, 1, 3), 256>>>(Wq, Wk, Wv);

    proj_kernel<<<dim3(4, 49, 3), 256, PJ_SMEM>>>(bq, bk, bv);

    retrieve_mma<<<4096, 256>>>();

    attn_kernel<<<dim3(HH, BB), 256, ATTN_SMEM>>>(out + OUT_PROBS);

    logits_kernel<<<BB*BB, 256>>>(ls, out + OUT_LOGITS);

    ln_kernel<<<MM, 128>>>(q, gamma, beta, out + OUT_CTX);
}